// round 11
// baseline (speedup 1.0000x reference)
#include <cuda_runtime.h>
#include <math.h>

#define BSZ  1024
#define TLEN 256
#define HH   128
#define GG   384   // 3*H

// -------- scratch (static device globals; no runtime allocation) --------
__device__ float g_gi[(size_t)BSZ * TLEN * GG];    // 402 MB, reused for gi0 then gi1
__device__ float g_seq[(size_t)BSZ * TLEN * HH];   // 134 MB, layer-0 output sequence
__device__ float g_hlast[(size_t)BSZ * HH];        // layer-1 final hidden

typedef unsigned long long u64;

// ---- packed f32x2 helpers (sm_100+; ptxas never auto-fuses these) ----
__device__ __forceinline__ void fma2(u64& d, u64 a, u64 b) {
    asm("fma.rn.f32x2 %0, %1, %2, %0;" : "+l"(d) : "l"(a), "l"(b));
}
__device__ __forceinline__ u64 pack2(float x) {
    u64 r; asm("mov.b64 %0, {%1, %1};" : "=l"(r) : "f"(x)); return r;
}
__device__ __forceinline__ float2 unpack2(u64 v) {
    float2 r; asm("mov.b64 {%0, %1}, %2;" : "=f"(r.x), "=f"(r.y) : "l"(v)); return r;
}

__device__ __forceinline__ float fsigmoid(float x) {
    return __fdividef(1.f, 1.f + __expf(-x));
}
__device__ __forceinline__ float ftanh(float x) {
    return 1.f - __fdividef(2.f, __expf(2.f * x) + 1.f);
}

// =======================================================================
// GEMM (R5 known-good): g_gi[row][c] = sum_k X[row][k]*W[c][k] + bias[c]
// rows = 262144, N = 384, K in {153,128}. 64-row tile, 256 threads,
// thread tile 8 rows x 6 col-PAIRS, packed f32x2 FMA.
// =======================================================================
__global__ void __launch_bounds__(256) gemm384(
    const float* __restrict__ Xext, int useSeq, int K,
    const float* __restrict__ W, const float* __restrict__ bias)
{
    const float* __restrict__ X = useSeq ? g_seq : Xext;
    __shared__ float xs[64][16];     // [row][kk]
    __shared__ float ws[16][386];    // [kk][col], pad 386 -> conflict-free
    int tid = threadIdx.x;
    size_t row0 = (size_t)blockIdx.x * 64;
    int tr = (tid >> 5) * 8;     // thread row base within tile
    int tc = tid & 31;           // col-pair base; cols {2tc,2tc+1} + 64*j

    u64 acc[8][6];
#pragma unroll
    for (int r = 0; r < 8; r++)
#pragma unroll
        for (int j = 0; j < 6; j++) acc[r][j] = 0ull;

    for (int k0 = 0; k0 < K; k0 += 16) {
#pragma unroll
        for (int i = tid; i < 64 * 16; i += 256) {
            int r = i >> 4, kk = i & 15;
            int k = k0 + kk;
            xs[r][kk] = (k < K) ? X[(row0 + r) * (size_t)K + k] : 0.f;
        }
#pragma unroll
        for (int i = tid; i < 384 * 16; i += 256) {
            int c = i >> 4, kk = i & 15;
            int k = k0 + kk;
            ws[kk][c] = (k < K) ? W[(size_t)c * K + k] : 0.f;
        }
        __syncthreads();
#pragma unroll
        for (int kk = 0; kk < 16; kk++) {
            u64 wv[6];
#pragma unroll
            for (int j = 0; j < 6; j++)
                wv[j] = *(const u64*)&ws[kk][2 * tc + 64 * j];
#pragma unroll
            for (int r = 0; r < 8; r++) {
                u64 xp = pack2(xs[tr + r][kk]);
#pragma unroll
                for (int j = 0; j < 6; j++)
                    fma2(acc[r][j], xp, wv[j]);
            }
        }
        __syncthreads();
    }
#pragma unroll
    for (int j = 0; j < 6; j++) {
        int c = 2 * tc + 64 * j;
        float2 bv = make_float2(bias[c], bias[c + 1]);
#pragma unroll
        for (int r = 0; r < 8; r++) {
            float2 v = unpack2(acc[r][j]);
            v.x += bv.x; v.y += bv.y;
            *(float2*)&g_gi[(row0 + tr + r) * (size_t)GG + c] = v;
        }
    }
}

// =======================================================================
// GRU recurrence v5. 128 CTAs x 8 batch rows; 384 threads.
//  - matvec team: warps 0-7 (256 thr), k-SPLIT: warps 0-3 own k in [0,64),
//    warps 4-7 own k in [64,128). Thread owns 3 cols x 4 row-pairs
//    (f32x2 accumulators, rows packed). W read ONCE per step total.
//  - gate team: warps 8-11 (128 thr). Thread owns row r=gt>>4, 8 units
//    jb..jb+7. Sums the two k-partials, applies gates, updates h.
// smem: wk[128][385] + hp[4][256] + ghsh[384][18] = 228,864 B
// =======================================================================
#define WK_STRIDE 385
#define GH_STRIDE 18   // floats per col: half0 rows 0-7, half1 rows 8-15, pad 2
#define RECUR_SMEM ((128 * WK_STRIDE + 4 * 128 * 2 + 384 * GH_STRIDE) * (int)sizeof(float))

__global__ void __launch_bounds__(384) gru_recur(
    const float* __restrict__ Whh, const float* __restrict__ bhh, int writeSeq)
{
    extern __shared__ float smem[];
    float* wk   = smem;                        // [128][385]: wk[k*385+g] = Whh[g][k]
    float* hp   = smem + 128 * WK_STRIDE;      // [4][256]: row-pair dup {h_2rp, h_2rp+1}
    float* ghsh = hp + 4 * 128 * 2;            // [384][18]: gh partials per col

    int tid = threadIdx.x;
    size_t b0 = (size_t)blockIdx.x * 8;

    // load Whh transposed (one-time)
    for (int idx = tid; idx < GG * HH; idx += 384) {
        int g = idx >> 7, k = idx & 127;
        wk[k * WK_STRIDE + g] = Whh[idx];
    }
    for (int idx = tid; idx < 4 * 128 * 2; idx += 384) hp[idx] = 0.f;

    const bool mv = tid < 256;                 // matvec team
    const int kh  = tid >> 7;                  // 0/1 (valid for mv): k-half
    const int col = tid & 127;                 // cols col, col+128, col+256
    const int kbase = kh * 64;

    u64 bias2[3];
    if (mv) {
#pragma unroll
        for (int c = 0; c < 3; c++)
            bias2[c] = kh ? 0ull : pack2(bhh[col + 128 * c]);
    }

    // gate team mapping: gt in [0,128)
    int gt = tid - 256;
    int gr = gt >> 4;                          // row 0..7
    int jb = (gt & 15) * 8;                    // unit base, 8 contiguous units

    float hreg[8];
#pragma unroll
    for (int u = 0; u < 8; u++) hreg[u] = 0.f;
    const float* gi_base = g_gi + ((b0 + gr) * TLEN) * (size_t)GG + jb;
    float* seq_base = g_seq + ((b0 + gr) * TLEN) * (size_t)HH + jb;

    __syncthreads();

    for (int t = 0; t < TLEN; t++) {
        if (mv) {
            // ---- matvec half: 32 k-pairs ----
            u64 acc[4][3];
#pragma unroll
            for (int rp = 0; rp < 4; rp++)
#pragma unroll
                for (int c = 0; c < 3; c++) acc[rp][c] = bias2[c];

            const float* wrow = wk + (size_t)kbase * WK_STRIDE + col;
#pragma unroll 4
            for (int kp = 0; kp < 32; kp++) {
                int k2 = 2 * kp;
                u64 wd0[3], wd1[3];
#pragma unroll
                for (int c = 0; c < 3; c++) {
                    wd0[c] = pack2(wrow[(size_t)k2 * WK_STRIDE + 128 * c]);
                    wd1[c] = pack2(wrow[(size_t)(k2 + 1) * WK_STRIDE + 128 * c]);
                }
#pragma unroll
                for (int rp = 0; rp < 4; rp++) {
                    // {h_2rp(k),h_2rp+1(k),h_2rp(k+1),h_2rp+1(k+1)} broadcast
                    ulonglong2 h2 = *(const ulonglong2*)(hp + rp * 256 + 2 * (kbase + k2));
#pragma unroll
                    for (int c = 0; c < 3; c++) {
                        fma2(acc[rp][c], h2.x, wd0[c]);
                        fma2(acc[rp][c], h2.y, wd1[c]);
                    }
                }
            }
            // stage partials: half kh at float offset kh*8 + 2*rp (u64-aligned)
#pragma unroll
            for (int c = 0; c < 3; c++)
#pragma unroll
                for (int rp = 0; rp < 4; rp++)
                    *(u64*)(ghsh + (col + 128 * c) * GH_STRIDE + kh * 8 + 2 * rp) = acc[rp][c];
        } else {
            // gi prefetch: LDGs issue here, latency hidden under matvec
            // (stored into hreg-adjacent regs; consumed after the barrier)
        }
        // gate team loads gi concurrently with matvec compute
        float4 giA0, giA1, giB0, giB1, giC0, giC1;
        if (!mv) {
            const float* gp = gi_base + (size_t)t * GG;
            giA0 = *(const float4*)(gp);
            giA1 = *(const float4*)(gp + 4);
            giB0 = *(const float4*)(gp + 128);
            giB1 = *(const float4*)(gp + 132);
            giC0 = *(const float4*)(gp + 256);
            giC1 = *(const float4*)(gp + 260);
        }
        __syncthreads();

        if (!mv) {
            float gi_r[8] = {giA0.x, giA0.y, giA0.z, giA0.w, giA1.x, giA1.y, giA1.z, giA1.w};
            float gi_z[8] = {giB0.x, giB0.y, giB0.z, giB0.w, giB1.x, giB1.y, giB1.z, giB1.w};
            float gi_n[8] = {giC0.x, giC0.y, giC0.z, giC0.w, giC1.x, giC1.y, giC1.z, giC1.w};
            float hn[8];
#pragma unroll
            for (int u = 0; u < 8; u++) {
                int j = jb + u;
                const float* g0 = ghsh + j * GH_STRIDE + gr;
                const float* g1 = ghsh + (j + 128) * GH_STRIDE + gr;
                const float* g2 = ghsh + (j + 256) * GH_STRIDE + gr;
                float ghr = g0[0] + g0[8];
                float ghz = g1[0] + g1[8];
                float ghn = g2[0] + g2[8];
                float r = fsigmoid(gi_r[u] + ghr);
                float z = fsigmoid(gi_z[u] + ghz);
                float n = ftanh(gi_n[u] + r * ghn);
                hn[u] = (1.f - z) * n + z * hreg[u];
                hreg[u] = hn[u];
            }
            // write new h into row-pair dup layout
            int rp = gr >> 1, half = gr & 1;
#pragma unroll
            for (int u = 0; u < 8; u++)
                hp[rp * 256 + 2 * (jb + u) + half] = hn[u];
            if (writeSeq) {
                float* sp = seq_base + (size_t)t * HH;
                *(float4*)(sp)     = make_float4(hn[0], hn[1], hn[2], hn[3]);
                *(float4*)(sp + 4) = make_float4(hn[4], hn[5], hn[6], hn[7]);
            }
        }
        __syncthreads();
    }

    if (!writeSeq && !mv) {
        float* hl = g_hlast + (b0 + gr) * HH + jb;
        *(float4*)(hl)     = make_float4(hreg[0], hreg[1], hreg[2], hreg[3]);
        *(float4*)(hl + 4) = make_float4(hreg[4], hreg[5], hreg[6], hreg[7]);
    }
}

// =======================================================================
// Head: out[b] = sigmoid( relu(h_last[b] @ W1^T + b1) @ W2^T + b2 )
// =======================================================================
__global__ void __launch_bounds__(64) head_kernel(
    const float* __restrict__ W1, const float* __restrict__ b1,
    const float* __restrict__ W2, const float* __restrict__ b2,
    float* __restrict__ out)
{
    int b = blockIdx.x;
    int c = threadIdx.x;  // 0..63
    const float* hb = g_hlast + (size_t)b * HH;
    const float* wr = W1 + (size_t)c * HH;
    float acc = b1[c];
#pragma unroll
    for (int k = 0; k < HH; k += 4) {
        float4 hv = *(const float4*)(hb + k);
        float4 wv = *(const float4*)(wr + k);
        acc = fmaf(hv.x, wv.x, acc);
        acc = fmaf(hv.y, wv.y, acc);
        acc = fmaf(hv.z, wv.z, acc);
        acc = fmaf(hv.w, wv.w, acc);
    }
    float v = fmaxf(acc, 0.f) * W2[c];
    __shared__ float red[64];
    red[c] = v;
    __syncthreads();
    if (c == 0) {
        float s = b2[0];
#pragma unroll
        for (int i = 0; i < 64; i++) s += red[i];
        out[b] = 1.f / (1.f + expf(-s));
    }
}

// =======================================================================
extern "C" void kernel_launch(void* const* d_in, const int* in_sizes, int n_in,
                              void* d_out, int out_size)
{
    const float* x     = (const float*)d_in[0];
    const float* W_ih0 = (const float*)d_in[1];
    const float* W_hh0 = (const float*)d_in[2];
    const float* b_ih0 = (const float*)d_in[3];
    const float* b_hh0 = (const float*)d_in[4];
    const float* W_ih1 = (const float*)d_in[5];
    const float* W_hh1 = (const float*)d_in[6];
    const float* b_ih1 = (const float*)d_in[7];
    const float* b_hh1 = (const float*)d_in[8];
    const float* W1    = (const float*)d_in[9];
    const float* b1    = (const float*)d_in[10];
    const float* W2    = (const float*)d_in[11];
    const float* b2    = (const float*)d_in[12];
    float* out = (float*)d_out;

    cudaFuncSetAttribute(gru_recur, cudaFuncAttributeMaxDynamicSharedMemorySize,
                         RECUR_SMEM);

    const int M_TILES = (BSZ * TLEN) / 64;  // 4096

    gemm384<<<M_TILES, 256>>>(x, 0, 153, W_ih0, b_ih0);
    gru_recur<<<128, 384, RECUR_SMEM>>>(W_hh0, b_hh0, 1);
    gemm384<<<M_TILES, 256>>>(nullptr, 1, 128, W_ih1, b_ih1);
    gru_recur<<<128, 384, RECUR_SMEM>>>(W_hh1, b_hh1, 0);
    head_kernel<<<BSZ, 64>>>(W1, b1, W2, b2, out);
}

// round 12
// speedup vs baseline: 1.2830x; 1.2830x over previous
#include <cuda_runtime.h>
#include <math.h>

#define BSZ  1024
#define TLEN 256
#define HH   128
#define GG   384   // 3*H

// -------- scratch (static device globals; no runtime allocation) --------
__device__ float g_gi[(size_t)BSZ * TLEN * GG];    // 402 MB, reused for gi0 then gi1
__device__ float g_seq[(size_t)BSZ * TLEN * HH];   // 134 MB, layer-0 output sequence
__device__ float g_hlast[(size_t)BSZ * HH];        // layer-1 final hidden
__device__ float g_wT[160 * GG];                   // W^T staging (k-major), 160 >= ceil16(153)

typedef unsigned long long u64;
typedef unsigned int u32;

// ---- packed f32x2 helpers (sm_100+; ptxas never auto-fuses these) ----
__device__ __forceinline__ void fma2(u64& d, u64 a, u64 b) {
    asm("fma.rn.f32x2 %0, %1, %2, %0;" : "+l"(d) : "l"(a), "l"(b));
}
__device__ __forceinline__ u64 pack2(float x) {
    u64 r; asm("mov.b64 %0, {%1, %1};" : "=l"(r) : "f"(x)); return r;
}
__device__ __forceinline__ float2 unpack2(u64 v) {
    float2 r; asm("mov.b64 {%0, %1}, %2;" : "=f"(r.x), "=f"(r.y) : "l"(v)); return r;
}

__device__ __forceinline__ float fsigmoid(float x) {
    return __fdividef(1.f, 1.f + __expf(-x));
}
__device__ __forceinline__ float ftanh(float x) {
    return 1.f - __fdividef(2.f, __expf(2.f * x) + 1.f);
}

// ---- cp.async helpers ----
__device__ __forceinline__ void cp4(u32 saddr, const void* gaddr, bool valid) {
    int sz = valid ? 4 : 0;
    asm volatile("cp.async.ca.shared.global [%0], [%1], 4, %2;"
                 :: "r"(saddr), "l"(gaddr), "r"(sz) : "memory");
}
__device__ __forceinline__ void cp16(u32 saddr, const void* gaddr, bool valid) {
    int sz = valid ? 16 : 0;
    asm volatile("cp.async.cg.shared.global [%0], [%1], 16, %2;"
                 :: "r"(saddr), "l"(gaddr), "r"(sz) : "memory");
}
#define CP_COMMIT() asm volatile("cp.async.commit_group;" ::: "memory")

// =======================================================================
// One-time W transpose: g_wT[k][c] = W[c][k]. grid K, block 384.
// =======================================================================
__global__ void transposeW(const float* __restrict__ W, int K) {
    int k = blockIdx.x, c = threadIdx.x;
    g_wT[(size_t)k * GG + c] = W[(size_t)c * K + k];
}

// =======================================================================
// GEMM v2 (cp.async double-buffered): g_gi[row][c] = X@W^T + bias.
// rows = 262144, N = 384, K in {153,128}. 64-row tile, 256 threads,
// thread tile 8 rows x 6 col-PAIRS, packed f32x2 FMA.
// smem: 2 stages x (xs 64x16 + ws 16x384) = 57,344 B
// =======================================================================
#define XS_ST 1024            // floats per xs stage
#define WS_ST (16 * GG)       // floats per ws stage
#define GEMM_SMEM ((2 * XS_ST + 2 * WS_ST) * (int)sizeof(float))

__global__ void __launch_bounds__(256) gemm384(
    const float* __restrict__ Xext, int useSeq, int K,
    const float* __restrict__ bias)
{
    const float* __restrict__ X = useSeq ? g_seq : Xext;
    extern __shared__ float sm[];
    float* xs = sm;                 // [2][64][16]
    float* ws = sm + 2 * XS_ST;     // [2][16][384]
    u32 sbase = (u32)__cvta_generic_to_shared(sm);

    int tid = threadIdx.x;
    size_t row0 = (size_t)blockIdx.x * 64;
    int tr = (tid >> 5) * 8;     // thread row base within tile
    int tc = tid & 31;           // col-pair base; cols {2tc,2tc+1} + 64*j
    const int nchunks = (K + 15) / 16;

    // issue cp.async loads for chunk c into stage s
#define ISSUE(c, s) do {                                                      \
        int k0_ = (c) * 16;                                                   \
        _Pragma("unroll")                                                     \
        for (int i = 0; i < 4; i++) {                                         \
            int idx = tid + i * 256; int r = idx >> 4, kk = idx & 15;         \
            int k = k0_ + kk; bool v = (k < K);                               \
            size_t go = (row0 + r) * (size_t)K + (v ? k : 0);                 \
            cp4(sbase + ((s) * XS_ST + r * 16 + kk) * 4, X + go, v);          \
        }                                                                     \
        _Pragma("unroll")                                                     \
        for (int i = 0; i < 6; i++) {                                         \
            int uix = tid + i * 256; int kk = uix / 96, cu = uix % 96;        \
            int k = k0_ + kk; bool v = (k < K);                               \
            cp16(sbase + (2 * XS_ST + (s) * WS_ST + kk * GG + cu * 4) * 4,    \
                 g_wT + (size_t)k * GG + cu * 4, v);                          \
        }                                                                     \
        CP_COMMIT();                                                          \
    } while (0)

    u64 acc[8][6];
#pragma unroll
    for (int r = 0; r < 8; r++)
#pragma unroll
        for (int j = 0; j < 6; j++) acc[r][j] = 0ull;

    ISSUE(0, 0);

    for (int c = 0; c < nchunks; c++) {
        int s = c & 1;
        if (c + 1 < nchunks) {
            ISSUE(c + 1, s ^ 1);
            asm volatile("cp.async.wait_group 1;" ::: "memory");
        } else {
            asm volatile("cp.async.wait_group 0;" ::: "memory");
        }
        __syncthreads();

        const float* xsp = xs + s * XS_ST;
        const float* wsp = ws + s * WS_ST;
#pragma unroll
        for (int kk = 0; kk < 16; kk++) {
            u64 wv[6];
#pragma unroll
            for (int j = 0; j < 6; j++)
                wv[j] = *(const u64*)&wsp[kk * GG + 2 * tc + 64 * j];
#pragma unroll
            for (int r = 0; r < 8; r++) {
                u64 xp = pack2(xsp[(tr + r) * 16 + kk]);  // uniform broadcast
#pragma unroll
                for (int j = 0; j < 6; j++)
                    fma2(acc[r][j], xp, wv[j]);
            }
        }
        __syncthreads();
    }

#pragma unroll
    for (int j = 0; j < 6; j++) {
        int c = 2 * tc + 64 * j;
        float2 bv = make_float2(bias[c], bias[c + 1]);
#pragma unroll
        for (int r = 0; r < 8; r++) {
            float2 v = unpack2(acc[r][j]);
            v.x += bv.x; v.y += bv.y;
            *(float2*)&g_gi[(row0 + tr + r) * (size_t)GG + c] = v;
        }
    }
#undef ISSUE
}

// =======================================================================
// GRU recurrence v3 (R6 measured: 810us/layer). 128 CTAs x 8 batch rows;
// 384 threads. matvec team warps 0-3; gate team warps 4-11.
// =======================================================================
#define WK_STRIDE 385
#define GH_STRIDE 10
#define RECUR_SMEM ((128 * WK_STRIDE + 4 * 128 * 2 + 384 * GH_STRIDE) * (int)sizeof(float))

__global__ void __launch_bounds__(384) gru_recur(
    const float* __restrict__ Whh, const float* __restrict__ bhh, int writeSeq)
{
    extern __shared__ float smem[];
    float* wk   = smem;                        // [128][385]: wk[k*385+g] = Whh[g][k]
    float* hp   = smem + 128 * WK_STRIDE;      // [4][128] u64 row-pairs
    float* ghsh = hp + 4 * 128 * 2;            // [384][10]: gh[col][row] padded

    int tid = threadIdx.x;
    size_t b0 = (size_t)blockIdx.x * 8;

    for (int idx = tid; idx < GG * HH; idx += 384) {
        int g = idx >> 7, k = idx & 127;
        wk[k * WK_STRIDE + g] = Whh[idx];
    }
    for (int idx = tid; idx < 4 * 128 * 2; idx += 384) hp[idx] = 0.f;

    const bool mv = tid < 128;
    int col = tid;

    u64 bias2[3];
    if (mv) {
#pragma unroll
        for (int c = 0; c < 3; c++) bias2[c] = pack2(bhh[col + 128 * c]);
    }

    int t2 = tid - 128;
    int gr = t2 >> 5;
    int gl = t2 & 31;

    float hreg[4] = {0.f, 0.f, 0.f, 0.f};
    const float* gi_base = g_gi + ((b0 + gr) * TLEN) * (size_t)GG + gl;
    float* seq_base = g_seq + ((b0 + gr) * TLEN) * (size_t)HH + gl;

    __syncthreads();

    for (int t = 0; t < TLEN; t++) {
        float gi_v[12];
        if (!mv) {
            const float* gp = gi_base + (size_t)t * GG;
#pragma unroll
            for (int gidx = 0; gidx < 3; gidx++)
#pragma unroll
                for (int u = 0; u < 4; u++)
                    gi_v[gidx * 4 + u] = gp[gidx * 128 + u * 32];
        } else {
            u64 acc[4][3];
#pragma unroll
            for (int rp = 0; rp < 4; rp++)
#pragma unroll
                for (int c = 0; c < 3; c++) acc[rp][c] = bias2[c];

#pragma unroll 4
            for (int k = 0; k < HH; k += 2) {
                u64 wd0[3], wd1[3];
#pragma unroll
                for (int c = 0; c < 3; c++) {
                    wd0[c] = pack2(wk[k * WK_STRIDE + col + 128 * c]);
                    wd1[c] = pack2(wk[(k + 1) * WK_STRIDE + col + 128 * c]);
                }
#pragma unroll
                for (int rp = 0; rp < 4; rp++) {
                    ulonglong2 h2 = *(const ulonglong2*)(hp + rp * 256 + 2 * k);
#pragma unroll
                    for (int c = 0; c < 3; c++) {
                        fma2(acc[rp][c], h2.x, wd0[c]);
                        fma2(acc[rp][c], h2.y, wd1[c]);
                    }
                }
            }
#pragma unroll
            for (int c = 0; c < 3; c++)
#pragma unroll
                for (int rp = 0; rp < 4; rp++)
                    *(u64*)(ghsh + (col + 128 * c) * GH_STRIDE + 2 * rp) = acc[rp][c];
        }
        __syncthreads();

        if (!mv) {
            int rsel = (gr >> 1) * 2 + (gr & 1);
            float hn[4];
#pragma unroll
            for (int u = 0; u < 4; u++) {
                int j = gl + 32 * u;
                float ghr = ghsh[j * GH_STRIDE + rsel];
                float ghz = ghsh[(j + 128) * GH_STRIDE + rsel];
                float ghn = ghsh[(j + 256) * GH_STRIDE + rsel];
                float r = fsigmoid(gi_v[u] + ghr);
                float z = fsigmoid(gi_v[4 + u] + ghz);
                float n = ftanh(gi_v[8 + u] + r * ghn);
                hn[u] = (1.f - z) * n + z * hreg[u];
                hreg[u] = hn[u];
            }
            int rp = gr >> 1, half = gr & 1;
#pragma unroll
            for (int u = 0; u < 4; u++) {
                int j = gl + 32 * u;
                hp[rp * 256 + 2 * j + half] = hn[u];
            }
            if (writeSeq) {
                float* sp = seq_base + (size_t)t * HH;
#pragma unroll
                for (int u = 0; u < 4; u++) sp[u * 32] = hn[u];
            }
        }
        __syncthreads();
    }

    if (!writeSeq && !mv) {
        float* hl = g_hlast + (b0 + gr) * HH + gl;
#pragma unroll
        for (int u = 0; u < 4; u++) hl[u * 32] = hreg[u];
    }
}

// =======================================================================
// Head: out[b] = sigmoid( relu(h_last[b] @ W1^T + b1) @ W2^T + b2 )
// =======================================================================
__global__ void __launch_bounds__(64) head_kernel(
    const float* __restrict__ W1, const float* __restrict__ b1,
    const float* __restrict__ W2, const float* __restrict__ b2,
    float* __restrict__ out)
{
    int b = blockIdx.x;
    int c = threadIdx.x;  // 0..63
    const float* hb = g_hlast + (size_t)b * HH;
    const float* wr = W1 + (size_t)c * HH;
    float acc = b1[c];
#pragma unroll
    for (int k = 0; k < HH; k += 4) {
        float4 hv = *(const float4*)(hb + k);
        float4 wv = *(const float4*)(wr + k);
        acc = fmaf(hv.x, wv.x, acc);
        acc = fmaf(hv.y, wv.y, acc);
        acc = fmaf(hv.z, wv.z, acc);
        acc = fmaf(hv.w, wv.w, acc);
    }
    float v = fmaxf(acc, 0.f) * W2[c];
    __shared__ float red[64];
    red[c] = v;
    __syncthreads();
    if (c == 0) {
        float s = b2[0];
#pragma unroll
        for (int i = 0; i < 64; i++) s += red[i];
        out[b] = 1.f / (1.f + expf(-s));
    }
}

// =======================================================================
extern "C" void kernel_launch(void* const* d_in, const int* in_sizes, int n_in,
                              void* d_out, int out_size)
{
    const float* x     = (const float*)d_in[0];
    const float* W_ih0 = (const float*)d_in[1];
    const float* W_hh0 = (const float*)d_in[2];
    const float* b_ih0 = (const float*)d_in[3];
    const float* b_hh0 = (const float*)d_in[4];
    const float* W_ih1 = (const float*)d_in[5];
    const float* W_hh1 = (const float*)d_in[6];
    const float* b_ih1 = (const float*)d_in[7];
    const float* b_hh1 = (const float*)d_in[8];
    const float* W1    = (const float*)d_in[9];
    const float* b1    = (const float*)d_in[10];
    const float* W2    = (const float*)d_in[11];
    const float* b2    = (const float*)d_in[12];
    float* out = (float*)d_out;

    cudaFuncSetAttribute(gru_recur, cudaFuncAttributeMaxDynamicSharedMemorySize,
                         RECUR_SMEM);
    cudaFuncSetAttribute(gemm384, cudaFuncAttributeMaxDynamicSharedMemorySize,
                         GEMM_SMEM);

    const int M_TILES = (BSZ * TLEN) / 64;  // 4096

    // layer 0: transpose W_ih0, input projection, recurrence
    transposeW<<<153, GG>>>(W_ih0, 153);
    gemm384<<<M_TILES, 256, GEMM_SMEM>>>(x, 0, 153, b_ih0);
    gru_recur<<<128, 384, RECUR_SMEM>>>(W_hh0, b_hh0, 1);
    // layer 1: transpose W_ih1, input projection, recurrence
    transposeW<<<128, GG>>>(W_ih1, 128);
    gemm384<<<M_TILES, 256, GEMM_SMEM>>>(nullptr, 1, 128, b_ih1);
    gru_recur<<<128, 384, RECUR_SMEM>>>(W_hh1, b_hh1, 0);
    // classifier head
    head_kernel<<<BSZ, 64>>>(W1, b1, W2, b2, out);
}

// round 13
// speedup vs baseline: 1.3017x; 1.0145x over previous
#include <cuda_runtime.h>
#include <math.h>

#define BSZ  1024
#define TLEN 256
#define HH   128
#define GG   384   // 3*H

// -------- scratch (static device globals; no runtime allocation) --------
__device__ float g_gi[(size_t)BSZ * TLEN * GG];    // 402 MB, reused for gi0 then gi1
__device__ float g_seq[(size_t)BSZ * TLEN * HH];   // 134 MB, layer-0 output sequence
__device__ float g_hlast[(size_t)BSZ * HH];        // layer-1 final hidden
__device__ float g_wT[2][160 * GG];                // W^T staging (k-major), per layer

typedef unsigned long long u64;
typedef unsigned int u32;

// ---- packed f32x2 helpers (sm_100+; ptxas never auto-fuses these) ----
__device__ __forceinline__ void fma2(u64& d, u64 a, u64 b) {
    asm("fma.rn.f32x2 %0, %1, %2, %0;" : "+l"(d) : "l"(a), "l"(b));
}
__device__ __forceinline__ u64 pack2(float x) {
    u64 r; asm("mov.b64 %0, {%1, %1};" : "=l"(r) : "f"(x)); return r;
}
__device__ __forceinline__ float2 unpack2(u64 v) {
    float2 r; asm("mov.b64 {%0, %1}, %2;" : "=f"(r.x), "=f"(r.y) : "l"(v)); return r;
}

__device__ __forceinline__ float fsigmoid(float x) {
    return __fdividef(1.f, 1.f + __expf(-x));
}
__device__ __forceinline__ float ftanh(float x) {
    return 1.f - __fdividef(2.f, __expf(2.f * x) + 1.f);
}

// ---- cp.async helpers ----
__device__ __forceinline__ void cp4(u32 saddr, const void* gaddr, bool valid) {
    int sz = valid ? 4 : 0;
    asm volatile("cp.async.ca.shared.global [%0], [%1], 4, %2;"
                 :: "r"(saddr), "l"(gaddr), "r"(sz) : "memory");
}
__device__ __forceinline__ void cp16(u32 saddr, const void* gaddr, bool valid) {
    int sz = valid ? 16 : 0;
    asm volatile("cp.async.cg.shared.global [%0], [%1], 16, %2;"
                 :: "r"(saddr), "l"(gaddr), "r"(sz) : "memory");
}
#define CP_COMMIT() asm volatile("cp.async.commit_group;" ::: "memory")

// =======================================================================
// One-time W transpose: g_wT[slot][k][c] = W[c][k]. grid K, block 384.
// =======================================================================
__global__ void transposeW(const float* __restrict__ W, int K, int slot) {
    int k = blockIdx.x, c = threadIdx.x;
    g_wT[slot][(size_t)k * GG + c] = W[(size_t)c * K + k];
}

// =======================================================================
// GEMM v3 (cp.async 3-stage, 32-row tiles, 2 CTAs/SM):
// g_gi[row][c] = X@W^T + bias. rows = 262144, N = 384, K in {153,128}.
// 256 threads, thread tile 4 rows x 6 col-PAIRS, packed f32x2 FMA.
// smem: 3 stages x (xs 32x16 + ws 16x384) = 79.9 KB
// =======================================================================
#define XS_ST 512             // floats per xs stage
#define WS_ST (16 * GG)       // floats per ws stage
#define STG   (XS_ST + WS_ST)
#define GEMM_SMEM (3 * STG * (int)sizeof(float))

__global__ void __launch_bounds__(256) gemm384(
    const float* __restrict__ Xext, int useSeq, int K, int slot,
    const float* __restrict__ bias)
{
    const float* __restrict__ X = useSeq ? g_seq : Xext;
    const float* __restrict__ WT = g_wT[slot];
    extern __shared__ float sm[];
    // stage s: xs at s*STG, ws at s*STG + XS_ST
    u32 sbase = (u32)__cvta_generic_to_shared(sm);

    int tid = threadIdx.x;
    size_t row0 = (size_t)blockIdx.x * 32;
    int tr = (tid >> 5) * 4;     // thread row base within tile
    int tc = tid & 31;           // col-pair base; cols {2tc,2tc+1} + 64*j
    const int nch = (K + 15) / 16;

#define ISSUE(c, s) do {                                                      \
        int k0_ = (c) * 16;                                                   \
        _Pragma("unroll")                                                     \
        for (int i = 0; i < 2; i++) {                                         \
            int idx = tid + i * 256; int r = idx >> 4, kk = idx & 15;         \
            int k = k0_ + kk; bool v = (k < K);                               \
            size_t go = (row0 + r) * (size_t)K + (v ? k : 0);                 \
            cp4(sbase + ((s) * STG + r * 16 + kk) * 4, X + go, v);            \
        }                                                                     \
        _Pragma("unroll")                                                     \
        for (int i = 0; i < 6; i++) {                                         \
            int uix = tid + i * 256; int kk = uix / 96, cu = uix % 96;        \
            int k = k0_ + kk; bool v = (k < K);                               \
            cp16(sbase + ((s) * STG + XS_ST + kk * GG + cu * 4) * 4,          \
                 WT + (size_t)k * GG + cu * 4, v);                            \
        }                                                                     \
        CP_COMMIT();                                                          \
    } while (0)

    u64 acc[4][6];
#pragma unroll
    for (int r = 0; r < 4; r++)
#pragma unroll
        for (int j = 0; j < 6; j++) acc[r][j] = 0ull;

    ISSUE(0, 0);
    if (nch > 1) ISSUE(1, 1);

    for (int c = 0; c < nch; c++) {
        int s = c % 3;
        if (c + 2 < nch) {
            ISSUE(c + 2, (c + 2) % 3);
            asm volatile("cp.async.wait_group 2;" ::: "memory");
        } else if (c + 1 < nch) {
            asm volatile("cp.async.wait_group 1;" ::: "memory");
        } else {
            asm volatile("cp.async.wait_group 0;" ::: "memory");
        }
        __syncthreads();

        const float* xsp = sm + s * STG;
        const float* wsp = sm + s * STG + XS_ST;
#pragma unroll
        for (int kk = 0; kk < 16; kk++) {
            u64 wv[6];
#pragma unroll
            for (int j = 0; j < 6; j++)
                wv[j] = *(const u64*)&wsp[kk * GG + 2 * tc + 64 * j];
#pragma unroll
            for (int r = 0; r < 4; r++) {
                u64 xp = pack2(xsp[(tr + r) * 16 + kk]);  // uniform broadcast
#pragma unroll
                for (int j = 0; j < 6; j++)
                    fma2(acc[r][j], xp, wv[j]);
            }
        }
        __syncthreads();
    }

#pragma unroll
    for (int j = 0; j < 6; j++) {
        int c = 2 * tc + 64 * j;
        float2 bv = make_float2(bias[c], bias[c + 1]);
#pragma unroll
        for (int r = 0; r < 4; r++) {
            float2 v = unpack2(acc[r][j]);
            v.x += bv.x; v.y += bv.y;
            *(float2*)&g_gi[(row0 + tr + r) * (size_t)GG + c] = v;
        }
    }
#undef ISSUE
}

// =======================================================================
// GRU recurrence v3 (measured 810us/layer). 128 CTAs x 8 batch rows;
// 384 threads. matvec team warps 0-3; gate team warps 4-11.
// =======================================================================
#define WK_STRIDE 385
#define GH_STRIDE 10
#define RECUR_SMEM ((128 * WK_STRIDE + 4 * 128 * 2 + 384 * GH_STRIDE) * (int)sizeof(float))

__global__ void __launch_bounds__(384) gru_recur(
    const float* __restrict__ Whh, const float* __restrict__ bhh, int writeSeq)
{
    extern __shared__ float smem[];
    float* wk   = smem;                        // [128][385]: wk[k*385+g] = Whh[g][k]
    float* hp   = smem + 128 * WK_STRIDE;      // [4][128] u64 row-pairs
    float* ghsh = hp + 4 * 128 * 2;            // [384][10]: gh[col][row] padded

    int tid = threadIdx.x;
    size_t b0 = (size_t)blockIdx.x * 8;

    for (int idx = tid; idx < GG * HH; idx += 384) {
        int g = idx >> 7, k = idx & 127;
        wk[k * WK_STRIDE + g] = Whh[idx];
    }
    for (int idx = tid; idx < 4 * 128 * 2; idx += 384) hp[idx] = 0.f;

    const bool mv = tid < 128;
    int col = tid;

    u64 bias2[3];
    if (mv) {
#pragma unroll
        for (int c = 0; c < 3; c++) bias2[c] = pack2(bhh[col + 128 * c]);
    }

    int t2 = tid - 128;
    int gr = t2 >> 5;
    int gl = t2 & 31;

    float hreg[4] = {0.f, 0.f, 0.f, 0.f};
    const float* gi_base = g_gi + ((b0 + gr) * TLEN) * (size_t)GG + gl;
    float* seq_base = g_seq + ((b0 + gr) * TLEN) * (size_t)HH + gl;

    __syncthreads();

    for (int t = 0; t < TLEN; t++) {
        float gi_v[12];
        if (!mv) {
            const float* gp = gi_base + (size_t)t * GG;
#pragma unroll
            for (int gidx = 0; gidx < 3; gidx++)
#pragma unroll
                for (int u = 0; u < 4; u++)
                    gi_v[gidx * 4 + u] = gp[gidx * 128 + u * 32];
        } else {
            u64 acc[4][3];
#pragma unroll
            for (int rp = 0; rp < 4; rp++)
#pragma unroll
                for (int c = 0; c < 3; c++) acc[rp][c] = bias2[c];

#pragma unroll 4
            for (int k = 0; k < HH; k += 2) {
                u64 wd0[3], wd1[3];
#pragma unroll
                for (int c = 0; c < 3; c++) {
                    wd0[c] = pack2(wk[k * WK_STRIDE + col + 128 * c]);
                    wd1[c] = pack2(wk[(k + 1) * WK_STRIDE + col + 128 * c]);
                }
#pragma unroll
                for (int rp = 0; rp < 4; rp++) {
                    ulonglong2 h2 = *(const ulonglong2*)(hp + rp * 256 + 2 * k);
#pragma unroll
                    for (int c = 0; c < 3; c++) {
                        fma2(acc[rp][c], h2.x, wd0[c]);
                        fma2(acc[rp][c], h2.y, wd1[c]);
                    }
                }
            }
#pragma unroll
            for (int c = 0; c < 3; c++)
#pragma unroll
                for (int rp = 0; rp < 4; rp++)
                    *(u64*)(ghsh + (col + 128 * c) * GH_STRIDE + 2 * rp) = acc[rp][c];
        }
        __syncthreads();

        if (!mv) {
            int rsel = (gr >> 1) * 2 + (gr & 1);
            float hn[4];
#pragma unroll
            for (int u = 0; u < 4; u++) {
                int j = gl + 32 * u;
                float ghr = ghsh[j * GH_STRIDE + rsel];
                float ghz = ghsh[(j + 128) * GH_STRIDE + rsel];
                float ghn = ghsh[(j + 256) * GH_STRIDE + rsel];
                float r = fsigmoid(gi_v[u] + ghr);
                float z = fsigmoid(gi_v[4 + u] + ghz);
                float n = ftanh(gi_v[8 + u] + r * ghn);
                hn[u] = (1.f - z) * n + z * hreg[u];
                hreg[u] = hn[u];
            }
            int rp = gr >> 1, half = gr & 1;
#pragma unroll
            for (int u = 0; u < 4; u++) {
                int j = gl + 32 * u;
                hp[rp * 256 + 2 * j + half] = hn[u];
            }
            if (writeSeq) {
                float* sp = seq_base + (size_t)t * HH;
#pragma unroll
                for (int u = 0; u < 4; u++) sp[u * 32] = hn[u];
            }
        }
        __syncthreads();
    }

    if (!writeSeq && !mv) {
        float* hl = g_hlast + (b0 + gr) * HH + gl;
#pragma unroll
        for (int u = 0; u < 4; u++) hl[u * 32] = hreg[u];
    }
}

// =======================================================================
// Head: out[b] = sigmoid( relu(h_last[b] @ W1^T + b1) @ W2^T + b2 )
// =======================================================================
__global__ void __launch_bounds__(64) head_kernel(
    const float* __restrict__ W1, const float* __restrict__ b1,
    const float* __restrict__ W2, const float* __restrict__ b2,
    float* __restrict__ out)
{
    int b = blockIdx.x;
    int c = threadIdx.x;  // 0..63
    const float* hb = g_hlast + (size_t)b * HH;
    const float* wr = W1 + (size_t)c * HH;
    float acc = b1[c];
#pragma unroll
    for (int k = 0; k < HH; k += 4) {
        float4 hv = *(const float4*)(hb + k);
        float4 wv = *(const float4*)(wr + k);
        acc = fmaf(hv.x, wv.x, acc);
        acc = fmaf(hv.y, wv.y, acc);
        acc = fmaf(hv.z, wv.z, acc);
        acc = fmaf(hv.w, wv.w, acc);
    }
    float v = fmaxf(acc, 0.f) * W2[c];
    __shared__ float red[64];
    red[c] = v;
    __syncthreads();
    if (c == 0) {
        float s = b2[0];
#pragma unroll
        for (int i = 0; i < 64; i++) s += red[i];
        out[b] = 1.f / (1.f + expf(-s));
    }
}

// =======================================================================
extern "C" void kernel_launch(void* const* d_in, const int* in_sizes, int n_in,
                              void* d_out, int out_size)
{
    const float* x     = (const float*)d_in[0];
    const float* W_ih0 = (const float*)d_in[1];
    const float* W_hh0 = (const float*)d_in[2];
    const float* b_ih0 = (const float*)d_in[3];
    const float* b_hh0 = (const float*)d_in[4];
    const float* W_ih1 = (const float*)d_in[5];
    const float* W_hh1 = (const float*)d_in[6];
    const float* b_ih1 = (const float*)d_in[7];
    const float* b_hh1 = (const float*)d_in[8];
    const float* W1    = (const float*)d_in[9];
    const float* b1    = (const float*)d_in[10];
    const float* W2    = (const float*)d_in[11];
    const float* b2    = (const float*)d_in[12];
    float* out = (float*)d_out;

    cudaFuncSetAttribute(gru_recur, cudaFuncAttributeMaxDynamicSharedMemorySize,
                         RECUR_SMEM);
    cudaFuncSetAttribute(gemm384, cudaFuncAttributeMaxDynamicSharedMemorySize,
                         GEMM_SMEM);

    const int M_TILES = (BSZ * TLEN) / 32;  // 8192

    // both transposes up-front (independent of everything else)
    transposeW<<<153, GG>>>(W_ih0, 153, 0);
    transposeW<<<128, GG>>>(W_ih1, 128, 1);

    gemm384<<<M_TILES, 256, GEMM_SMEM>>>(x, 0, 153, 0, b_ih0);
    gru_recur<<<128, 384, RECUR_SMEM>>>(W_hh0, b_hh0, 1);
    gemm384<<<M_TILES, 256, GEMM_SMEM>>>(nullptr, 1, 128, 1, b_ih1);
    gru_recur<<<128, 384, RECUR_SMEM>>>(W_hh1, b_hh1, 0);
    head_kernel<<<BSZ, 64>>>(W1, b1, W2, b2, out);
}